// round 5
// baseline (speedup 1.0000x reference)
#include <cuda_runtime.h>
#include <cuda_bf16.h>
#include <cstdint>

// DistortionLoss, O(N) per row, telescoped + T-deferred:
//   loss = inv * [ T*sum_e g_e*P_e - sum_e g_e*P_e^2 + (1/3)*sum w_i^2*dz_i ]
//   g_e = z_{e+1}-z_{e-1}, P_e = exclusive w prefix, T = total w,
//   inv = 1/(far-near). e=0 term has P_0=0 (z_{-1} value irrelevant).
//
// z is staged block-wide through smem with LDG.128 (8 rows = 1032 contiguous
// floats, 16B-aligned) to minimize L1tex wavefronts; rows padded to 132 floats
// in smem so each lane reads its 4 z's as one aligned LDS.128.

#define FULL 0xffffffffu

constexpr int RPB  = 8;     // rows per block (256 threads, 1 warp/row)
constexpr int ZPAD = 132;   // padded smem row stride (16B-aligned rows)

__global__ __launch_bounds__(256)
void distortion_loss_kernel(const float* __restrict__ w,
                            const float* __restrict__ z,
                            const float* __restrict__ nearv,
                            const float* __restrict__ farv,
                            float* __restrict__ out,
                            int R)
{
    __shared__ __align__(16) float zbuf[RPB * ZPAD];

    const int tid  = threadIdx.x;
    const int wid  = tid >> 5;
    const int lane = tid & 31;
    const int row0 = blockIdx.x * RPB;
    const int row  = row0 + wid;

    // ---- issue independent per-warp loads BEFORE the staging barrier ----
    float4 w4 = make_float4(0.f, 0.f, 0.f, 0.f);
    float nr = 0.0f, fr = 1.0f;
    if (row < R) {
        w4 = reinterpret_cast<const float4*>(w + (size_t)row * 128)[lane];
        nr = __ldg(&nearv[row]);
        fr = __ldg(&farv[row]);
    }

    // ---- stage z for all 8 rows: 1032 floats = 258 LDG.128 ----
    const float* zbase = z + (size_t)row0 * 129;
    if (row0 + RPB <= R) {
        const float4* zsrc = reinterpret_cast<const float4*>(zbase);  // 16B-aligned
#pragma unroll
        for (int it = 0; it < 2; ++it) {
            const int idx = tid + it * 256;
            if (idx < 258) {
                const float4 v = __ldg(&zsrc[idx]);
                const int g = idx * 4;
                int r = g / 129;
                int c = g - r * 129;
                const float vals[4] = {v.x, v.y, v.z, v.w};
#pragma unroll
                for (int k = 0; k < 4; ++k) {
                    int cc = c + k, rr = r;
                    if (cc >= 129) { cc -= 129; rr += 1; }
                    zbuf[rr * ZPAD + cc] = vals[k];
                }
            }
        }
    } else {
        // tail block: scalar staging
        const int total = (R - row0) * 129;
        for (int i = tid; i < total; i += 256) {
            const int r = i / 129;
            const int c = i - r * 129;
            zbuf[r * ZPAD + c] = zbase[i];
        }
    }
    __syncthreads();

    if (row >= R) return;

    // ---- read this row's z from smem ----
    const float* zr = zbuf + wid * ZPAD;
    const int zi = lane * 4;
    const float4 zq = *reinterpret_cast<const float4*>(zr + zi);  // LDS.128
    const float zm1 = zr[(zi == 0) ? 0 : zi - 1];  // killed by P0=0 at lane 0
    const float z4v = zr[zi + 4];                  // max index 128, valid

    // ---- lane-local w prefixes ----
    const float pre1 = w4.x;
    const float pre2 = pre1 + w4.y;
    const float pre3 = pre2 + w4.z;
    const float wc   = pre3 + w4.w;

    // ---- warp inclusive scan of lane totals ----
    float wInc = wc;
#pragma unroll
    for (int o = 1; o < 32; o <<= 1) {
        float t = __shfl_up_sync(FULL, wInc, o);
        if (lane >= o) wInc += t;
    }
    const float Wex = wInc - wc;
    const float T   = __shfl_sync(FULL, wInc, 31);

    // ---- gaps + prefix products ----
    const float g0 = zq.y - zm1;
    const float g1 = zq.z - zq.x;
    const float g2 = zq.w - zq.y;
    const float g3 = z4v  - zq.z;

    const float P0 = Wex;
    const float P1 = Wex + pre1;
    const float P2 = Wex + pre2;
    const float P3 = Wex + pre3;

    const float t0 = g0 * P0;
    const float t1 = g1 * P1;
    const float t2 = g2 * P2;
    const float t3 = g3 * P3;

    float A = (t0 + t1) + (t2 + t3);

    float C;
    C =      (w4.x * w4.x) * (zq.y - zq.x);
    C = fmaf((w4.y * w4.y), (zq.z - zq.y), C);
    C = fmaf((w4.z * w4.z), (zq.w - zq.z), C);
    C = fmaf((w4.w * w4.w), (z4v  - zq.w), C);
    C *= (1.0f / 3.0f);
    C = fmaf(-t0, P0, C);
    C = fmaf(-t1, P1, C);
    C = fmaf(-t2, P2, C);
    C = fmaf(-t3, P3, C);

    // ---- interleaved independent butterflies ----
#pragma unroll
    for (int o = 16; o > 0; o >>= 1) {
        A += __shfl_xor_sync(FULL, A, o);
        C += __shfl_xor_sync(FULL, C, o);
    }

    if (lane == 0)
        out[row] = fmaf(T, A, C) * __fdividef(1.0f, fr - nr);
}

extern "C" void kernel_launch(void* const* d_in, const int* in_sizes, int n_in,
                              void* d_out, int out_size)
{
    const float* w  = (const float*)d_in[0];   // (R, 128, 1)
    const float* z  = (const float*)d_in[1];   // (R, 129)
    const float* nr = (const float*)d_in[2];   // (R, 1)
    const float* fr = (const float*)d_in[3];   // (R, 1)
    float* out = (float*)d_out;                // (R, 1)

    const int R = in_sizes[0] / 128;
    const int blocks = (R + RPB - 1) / RPB;    // 1024 for R=8192
    distortion_loss_kernel<<<blocks, 256>>>(w, z, nr, fr, out, R);
}

// round 6
// speedup vs baseline: 1.1345x; 1.1345x over previous
#include <cuda_runtime.h>
#include <cuda_bf16.h>
#include <cstdint>

// DistortionLoss, O(N) per row, telescoped + T-deferred:
//   loss = inv * [ T*sum_e g_e*P_e - sum_e g_e*P_e^2 + (1/3)*sum w_i^2*dz_i ]
//   g_e = z_{e+1}-z_{e-1}, P_e = exclusive w prefix, T = total w,
//   inv = 1/(far-near). e=0 term has P_0=0 (its z_{-1} is irrelevant).
//
// Persistent-ish warps: each warp processes rows in a grid-stride loop with
// software pipelining — next row's loads are issued before computing the
// current row, so DRAM latency overlaps the shfl-scan chain.

#define FULL 0xffffffffu

struct RowRegs {
    float4 w4;
    float z0, z1, z2, z3;
    float nr, fr;
};

__device__ __forceinline__ void load_row(const float* __restrict__ w,
                                         const float* __restrict__ z,
                                         const float* __restrict__ nearv,
                                         const float* __restrict__ farv,
                                         int row, int lane, RowRegs& R)
{
    const float* wr = w + (size_t)row * 128;
    const float* zr = z + (size_t)row * 129;
    R.w4 = __ldg(reinterpret_cast<const float4*>(wr) + lane);
    const int zi = lane * 4;
    R.z0 = __ldg(&zr[zi + 0]);
    R.z1 = __ldg(&zr[zi + 1]);
    R.z2 = __ldg(&zr[zi + 2]);
    R.z3 = __ldg(&zr[zi + 3]);
    R.nr = __ldg(&nearv[row]);
    R.fr = __ldg(&farv[row]);
    // lane 31 also needs z[128]; fold into z-edge via extra scalar load in compute
}

__device__ __forceinline__ void compute_row(const RowRegs& Rg,
                                            const float* __restrict__ z,
                                            int row, int lane,
                                            float* __restrict__ out)
{
    // boundary neighbors via shfl (avoids extra L1 wavefronts)
    float z4 = __shfl_down_sync(FULL, Rg.z0, 1);
    if (lane == 31) z4 = __ldg(&z[(size_t)row * 129 + 128]);
    const float zm1 = __shfl_up_sync(FULL, Rg.z3, 1);  // lane 0: killed by P0=0

    // lane-local w prefixes
    const float pre1 = Rg.w4.x;
    const float pre2 = pre1 + Rg.w4.y;
    const float pre3 = pre2 + Rg.w4.z;
    const float wc   = pre3 + Rg.w4.w;

    // warp inclusive scan of lane totals
    float wInc = wc;
#pragma unroll
    for (int o = 1; o < 32; o <<= 1) {
        float t = __shfl_up_sync(FULL, wInc, o);
        if (lane >= o) wInc += t;
    }
    const float Wex = wInc - wc;
    const float T   = __shfl_sync(FULL, wInc, 31);

    const float g0 = Rg.z1 - zm1;
    const float g1 = Rg.z2 - Rg.z0;
    const float g2 = Rg.z3 - Rg.z1;
    const float g3 = z4    - Rg.z2;

    const float P0 = Wex;
    const float P1 = Wex + pre1;
    const float P2 = Wex + pre2;
    const float P3 = Wex + pre3;

    const float t0 = g0 * P0;
    const float t1 = g1 * P1;
    const float t2 = g2 * P2;
    const float t3 = g3 * P3;

    float A = (t0 + t1) + (t2 + t3);

    float C;
    C =      (Rg.w4.x * Rg.w4.x) * (Rg.z1 - Rg.z0);
    C = fmaf((Rg.w4.y * Rg.w4.y), (Rg.z2 - Rg.z1), C);
    C = fmaf((Rg.w4.z * Rg.w4.z), (Rg.z3 - Rg.z2), C);
    C = fmaf((Rg.w4.w * Rg.w4.w), (z4    - Rg.z3), C);
    C *= (1.0f / 3.0f);
    C = fmaf(-t0, P0, C);
    C = fmaf(-t1, P1, C);
    C = fmaf(-t2, P2, C);
    C = fmaf(-t3, P3, C);

#pragma unroll
    for (int o = 16; o > 0; o >>= 1) {
        A += __shfl_xor_sync(FULL, A, o);
        C += __shfl_xor_sync(FULL, C, o);
    }

    if (lane == 0)
        out[row] = fmaf(T, A, C) * __fdividef(1.0f, Rg.fr - Rg.nr);
}

__global__ __launch_bounds__(256)
void distortion_loss_kernel(const float* __restrict__ w,
                            const float* __restrict__ z,
                            const float* __restrict__ nearv,
                            const float* __restrict__ farv,
                            float* __restrict__ out,
                            int R, int NW)
{
    const int gw   = (blockIdx.x * blockDim.x + threadIdx.x) >> 5;
    const int lane = threadIdx.x & 31;

    int row = gw;
    if (row >= R) return;

    RowRegs cur, nxt;
    load_row(w, z, nearv, farv, row, lane, cur);

    while (true) {
        const int next = row + NW;
        const bool haveNext = next < R;
        if (haveNext)
            load_row(w, z, nearv, farv, next, lane, nxt);  // overlaps compute below

        compute_row(cur, z, row, lane, out);

        if (!haveNext) break;
        cur = nxt;
        row = next;
    }
}

extern "C" void kernel_launch(void* const* d_in, const int* in_sizes, int n_in,
                              void* d_out, int out_size)
{
    const float* w  = (const float*)d_in[0];   // (R, 128, 1)
    const float* z  = (const float*)d_in[1];   // (R, 129)
    const float* nr = (const float*)d_in[2];   // (R, 1)
    const float* fr = (const float*)d_in[3];   // (R, 1)
    float* out = (float*)d_out;                // (R, 1)

    const int R = in_sizes[0] / 128;
    const int threads = 256;                   // 8 warps/CTA
    const int blocks  = 296;                   // ~2 CTAs/SM, 2368 warps total
    const int NW = blocks * (threads / 32);
    distortion_loss_kernel<<<blocks, threads>>>(w, z, nr, fr, out, R, NW);
}

// round 7
// speedup vs baseline: 1.2587x; 1.1095x over previous
#include <cuda_runtime.h>
#include <cuda_bf16.h>
#include <cstdint>

// DistortionLoss, O(N) per row, telescoped + T-deferred:
//   loss = inv * [ T*sum_e g_e*P_e - sum_e g_e*P_e^2 + (1/3)*sum w_i^2*dz_i ]
//   g_e = z_{e+1}-z_{e-1}, P_e = exclusive w prefix, T = total w,
//   inv = 1/(far-near). e=0 term has P_0=0 (its z_{-1} value is irrelevant).
//
// z loaded as ONE aligned LDG.128 per lane: row base (row*129-s)*4 bytes is
// 16B-aligned for s = row&3. Lane l's chunk holds z[4l-s .. 4l-s+3]; the true
// z[4l..4l+4] come from own chunk + next lane's chunk (shfl) + a warp-uniform
// select on s. Lane 31's tail (z[128-s..128], all in-bounds) via scalar loads.
// This minimizes L1tex wavefronts (~11/warp vs ~22 for strided scalar loads).

#define FULL 0xffffffffu

__global__ __launch_bounds__(256)
void distortion_loss_kernel(const float* __restrict__ w,
                            const float* __restrict__ z,
                            const float* __restrict__ nearv,
                            const float* __restrict__ farv,
                            float* __restrict__ out,
                            int R)
{
    const int row  = (blockIdx.x * blockDim.x + threadIdx.x) >> 5;
    const int lane = threadIdx.x & 31;
    if (row >= R) return;

    const int s = row & 3;                       // misalignment in floats
    const float* zrow = z + (size_t)row * 129;
    const float4* zc  = reinterpret_cast<const float4*>(zrow - s);  // 16B-aligned

    // ---- front-batched loads: 4-5 LDG instructions, ~11 wavefronts ----
    const float4 own = __ldg(zc + lane);                      // z[4l-s .. 4l-s+3]
    const float4 w4  = __ldg(reinterpret_cast<const float4*>(w + (size_t)row * 128) + lane);
    const float nr = __ldg(&nearv[row]);
    const float fr = __ldg(&farv[row]);

    // next lane's chunk; lane 31 patched with in-bounds tail scalars
    float4 nxt;
    nxt.x = __shfl_down_sync(FULL, own.x, 1);
    nxt.y = __shfl_down_sync(FULL, own.y, 1);
    nxt.z = __shfl_down_sync(FULL, own.z, 1);
    nxt.w = __shfl_down_sync(FULL, own.w, 1);
    if (lane == 31) {
        nxt.x = __ldg(zrow + 128 - s);           // element 128-s
        if (s >= 1) nxt.y = __ldg(zrow + 129 - s);
        if (s >= 2) nxt.z = __ldg(zrow + 130 - s);
        if (s == 3) nxt.w = __ldg(zrow + 128);
    }

    // warp-uniform select: z_j = element 4*lane + j
    float z0, z1, z2, z3, z4;
    switch (s) {
        case 0:  z0 = own.x; z1 = own.y; z2 = own.z; z3 = own.w; z4 = nxt.x; break;
        case 1:  z0 = own.y; z1 = own.z; z2 = own.w; z3 = nxt.x; z4 = nxt.y; break;
        case 2:  z0 = own.z; z1 = own.w; z2 = nxt.x; z3 = nxt.y; z4 = nxt.z; break;
        default: z0 = own.w; z1 = nxt.x; z2 = nxt.y; z3 = nxt.z; z4 = nxt.w; break;
    }
    const float zm1 = __shfl_up_sync(FULL, z3, 1);   // lane 0: killed by P0=0

    // ---- lane-local w prefixes ----
    const float pre1 = w4.x;
    const float pre2 = pre1 + w4.y;
    const float pre3 = pre2 + w4.z;
    const float wc   = pre3 + w4.w;

    // ---- warp inclusive scan of lane totals ----
    float wInc = wc;
#pragma unroll
    for (int o = 1; o < 32; o <<= 1) {
        float t = __shfl_up_sync(FULL, wInc, o);
        if (lane >= o) wInc += t;
    }
    const float Wex = wInc - wc;
    const float T   = __shfl_sync(FULL, wInc, 31);

    // ---- gaps + prefix products ----
    const float g0 = z1 - zm1;
    const float g1 = z2 - z0;
    const float g2 = z3 - z1;
    const float g3 = z4 - z2;

    const float P0 = Wex;
    const float P1 = Wex + pre1;
    const float P2 = Wex + pre2;
    const float P3 = Wex + pre3;

    const float t0 = g0 * P0;
    const float t1 = g1 * P1;
    const float t2 = g2 * P2;
    const float t3 = g3 * P3;

    const float A = (t0 + t1) + (t2 + t3);

    float C;
    C =      (w4.x * w4.x) * (z1 - z0);
    C = fmaf((w4.y * w4.y), (z2 - z1), C);
    C = fmaf((w4.z * w4.z), (z3 - z2), C);
    C = fmaf((w4.w * w4.w), (z4 - z3), C);
    C *= (1.0f / 3.0f);
    C = fmaf(-t0, P0, C);
    C = fmaf(-t1, P1, C);
    C = fmaf(-t2, P2, C);
    C = fmaf(-t3, P3, C);

    // T known to all lanes -> combine BEFORE a single butterfly
    float partial = fmaf(T, A, C);
#pragma unroll
    for (int o = 16; o > 0; o >>= 1)
        partial += __shfl_xor_sync(FULL, partial, o);

    if (lane == 0)
        out[row] = partial * __fdividef(1.0f, fr - nr);
}

extern "C" void kernel_launch(void* const* d_in, const int* in_sizes, int n_in,
                              void* d_out, int out_size)
{
    const float* w  = (const float*)d_in[0];   // (R, 128, 1)
    const float* z  = (const float*)d_in[1];   // (R, 129)
    const float* nr = (const float*)d_in[2];   // (R, 1)
    const float* fr = (const float*)d_in[3];   // (R, 1)
    float* out = (float*)d_out;                // (R, 1)

    const int R = in_sizes[0] / 128;
    const int threads = 256;                   // 8 warps = 8 rows per block
    const int blocks  = (R * 32 + threads - 1) / threads;
    distortion_loss_kernel<<<blocks, threads>>>(w, z, nr, fr, out, R);
}

// round 8
// speedup vs baseline: 1.3177x; 1.0469x over previous
#include <cuda_runtime.h>
#include <cuda_bf16.h>
#include <cstdint>

// DistortionLoss, O(N) per row, telescoped + T-deferred:
//   loss = inv * [ T*sum_e g_e*P_e - sum_e g_e*P_e^2 + (1/3)*sum w_i^2*dz_i ]
//   g_e = z_{e+1}-z_{e-1}, P_e = exclusive w prefix, T = total w,
//   inv = 1/(far-near). The e=0 term has P_0 = 0, so lane 0's zm1 is a
//   don't-care (any in-bounds value).
//
// z loaded as ONE aligned LDG.128 per lane from the 16B-floor base
// (row*129 - s, s = row&3). Lane l's chunk = z[4l-s .. 4l-s+3]. For s>=1,
// zm1 = z[4l-1] is already in the own chunk; only s+1 shfl_downs are needed
// to recover z[4l..4l+4] (avg 2.75 shfls vs 5). Lane 31's tail patched with
// in-bounds scalar loads. 512-thread blocks halve the CTA dispatch ramp.

#define FULL 0xffffffffu

__global__ __launch_bounds__(512)
void distortion_loss_kernel(const float* __restrict__ w,
                            const float* __restrict__ z,
                            const float* __restrict__ nearv,
                            const float* __restrict__ farv,
                            float* __restrict__ out,
                            int R)
{
    const int row  = (blockIdx.x * blockDim.x + threadIdx.x) >> 5;
    const int lane = threadIdx.x & 31;
    if (row >= R) return;

    const int s = row & 3;                                   // warp-uniform
    const float* zrow = z + (size_t)row * 129;
    const float4* zc  = reinterpret_cast<const float4*>(zrow - s);  // aligned

    // ---- front-batched loads ----
    const float4 own = __ldg(zc + lane);                     // z[4l-s .. 4l-s+3]
    const float4 w4  = __ldg(reinterpret_cast<const float4*>(w + (size_t)row * 128) + lane);
    const float nr = __ldg(&nearv[row]);
    const float fr = __ldg(&farv[row]);

    // ---- recover z[4l-1 .. 4l+4] with minimal shfls (warp-uniform switch) ----
    float zm1, z0, z1, z2, z3, z4;
    switch (s) {
        case 0: {
            float a = __shfl_down_sync(FULL, own.x, 1);      // z[4l+4]
            float b = __shfl_up_sync(FULL, own.w, 1);        // z[4l-1] (lane0 dc)
            if (lane == 31) a = __ldg(zrow + 128);
            zm1 = b; z0 = own.x; z1 = own.y; z2 = own.z; z3 = own.w; z4 = a;
        } break;
        case 1: {
            float a = __shfl_down_sync(FULL, own.x, 1);      // z[4l+3]
            float b = __shfl_down_sync(FULL, own.y, 1);      // z[4l+4]
            if (lane == 31) { a = __ldg(zrow + 127); b = __ldg(zrow + 128); }
            zm1 = own.x; z0 = own.y; z1 = own.z; z2 = own.w; z3 = a; z4 = b;
        } break;
        case 2: {
            float a = __shfl_down_sync(FULL, own.x, 1);      // z[4l+2]
            float b = __shfl_down_sync(FULL, own.y, 1);      // z[4l+3]
            float c = __shfl_down_sync(FULL, own.z, 1);      // z[4l+4]
            if (lane == 31) { a = __ldg(zrow + 126); b = __ldg(zrow + 127);
                              c = __ldg(zrow + 128); }
            zm1 = own.y; z0 = own.z; z1 = own.w; z2 = a; z3 = b; z4 = c;
        } break;
        default: {
            float a = __shfl_down_sync(FULL, own.x, 1);      // z[4l+1]
            float b = __shfl_down_sync(FULL, own.y, 1);      // z[4l+2]
            float c = __shfl_down_sync(FULL, own.z, 1);      // z[4l+3]
            float d = __shfl_down_sync(FULL, own.w, 1);      // z[4l+4]
            if (lane == 31) { a = __ldg(zrow + 125); b = __ldg(zrow + 126);
                              c = __ldg(zrow + 127); d = __ldg(zrow + 128); }
            zm1 = own.z; z0 = own.w; z1 = a; z2 = b; z3 = c; z4 = d;
        } break;
    }

    // ---- lane-local w prefixes ----
    const float pre1 = w4.x;
    const float pre2 = pre1 + w4.y;
    const float pre3 = pre2 + w4.z;
    const float wc   = pre3 + w4.w;

    // ---- warp inclusive scan of lane totals ----
    float wInc = wc;
#pragma unroll
    for (int o = 1; o < 32; o <<= 1) {
        float t = __shfl_up_sync(FULL, wInc, o);
        if (lane >= o) wInc += t;
    }
    const float Wex = wInc - wc;
    const float T   = __shfl_sync(FULL, wInc, 31);

    // ---- gaps + prefix products ----
    const float g0 = z1 - zm1;
    const float g1 = z2 - z0;
    const float g2 = z3 - z1;
    const float g3 = z4 - z2;

    const float P0 = Wex;
    const float P1 = Wex + pre1;
    const float P2 = Wex + pre2;
    const float P3 = Wex + pre3;

    const float t0 = g0 * P0;
    const float t1 = g1 * P1;
    const float t2 = g2 * P2;
    const float t3 = g3 * P3;

    const float A = (t0 + t1) + (t2 + t3);

    float C;
    C =      (w4.x * w4.x) * (z1 - z0);
    C = fmaf((w4.y * w4.y), (z2 - z1), C);
    C = fmaf((w4.z * w4.z), (z3 - z2), C);
    C = fmaf((w4.w * w4.w), (z4 - z3), C);
    C *= (1.0f / 3.0f);
    C = fmaf(-t0, P0, C);
    C = fmaf(-t1, P1, C);
    C = fmaf(-t2, P2, C);
    C = fmaf(-t3, P3, C);

    // T known to all lanes -> combine BEFORE a single butterfly
    float partial = fmaf(T, A, C);
#pragma unroll
    for (int o = 16; o > 0; o >>= 1)
        partial += __shfl_xor_sync(FULL, partial, o);

    if (lane == 0)
        out[row] = partial * __fdividef(1.0f, fr - nr);
}

extern "C" void kernel_launch(void* const* d_in, const int* in_sizes, int n_in,
                              void* d_out, int out_size)
{
    const float* w  = (const float*)d_in[0];   // (R, 128, 1)
    const float* z  = (const float*)d_in[1];   // (R, 129)
    const float* nr = (const float*)d_in[2];   // (R, 1)
    const float* fr = (const float*)d_in[3];   // (R, 1)
    float* out = (float*)d_out;                // (R, 1)

    const int R = in_sizes[0] / 128;
    const int threads = 512;                   // 16 warps = 16 rows per block
    const int blocks  = (R * 32 + threads - 1) / threads;   // 512 for R=8192
    distortion_loss_kernel<<<blocks, threads>>>(w, z, nr, fr, out, R);
}